// round 13
// baseline (speedup 1.0000x reference)
#include <cuda_runtime.h>
#include <cstdint>

// Problem constants (fixed by setup_inputs: B=2, Lq=16384, D=1024, M=64, H=16)
#define DMODEL 1024
#define ROWS   128            // B*M flattened rows
#define TPF    256            // Lq / M  (tokens per frame)

#define KSPLIT 16             // split-K factor
#define BK     64             // K per GEMM job
#define BN     128            // cols per GEMM job
#define NTILE  (DMODEL / BN)  // 8 column tiles
#define GRID   128            // persistent CTAs (= NTILE * KSPLIT)

// Scratch (static __device__ arrays — no runtime allocation)
__device__ float g_P[KSPLIT * ROWS * DMODEL];  // split-K partials (8 MB)
__device__ float g_V[ROWS * DMODEL];           // v = context @ Wkv_v + bkv_v
__device__ float g_Z[ROWS * DMODEL];           // z = v @ Wo + bo

// Grid-barrier state. MONOTONIC across launches — never reset (reset scheme
// deadlocked: a CTA still polling in the spin loop could observe the zeroed
// counter). Each launch's cohort releases at the next multiple of GRID.
__device__ unsigned g_bar[8];

__device__ __forceinline__ void grid_barrier(int ph) {
    __syncthreads();
    if (threadIdx.x == 0) {
        __threadfence();                                   // release prior writes
        const unsigned my = atomicAdd(&g_bar[ph], 1u) + 1u;
        const unsigned target = ((my + GRID - 1u) / GRID) * GRID;
        while (*(volatile unsigned*)&g_bar[ph] < target) { __nanosleep(32); }
        __threadfence();                                   // acquire others' writes
    }
    __syncthreads();
}

__device__ __forceinline__ uint32_t smem_u32(const void* p) {
    uint32_t a;
    asm("{ .reg .u64 t; cvta.to.shared.u64 t, %1; cvt.u32.u64 %0, t; }" : "=r"(a) : "l"(p));
    return a;
}

// ---------------------------------------------------------------------------
// tf32 helpers (mma.sync — baseline PTX, works at compute_100)
// ---------------------------------------------------------------------------
__device__ __forceinline__ uint32_t f2tf32(float f) {
    uint32_t r;
    asm("cvt.rna.tf32.f32 %0, %1;" : "=r"(r) : "f"(f));
    return r;
}
__device__ __forceinline__ void cvt_hilo(float f, uint32_t& hi, uint32_t& lo) {
    hi = f2tf32(f);
    lo = f2tf32(f - __uint_as_float(hi));
}
__device__ __forceinline__ void mma_tf32(float* d, const uint32_t* a, const uint32_t* b) {
    asm volatile(
        "mma.sync.aligned.m16n8k8.row.col.f32.tf32.tf32.f32 "
        "{%0,%1,%2,%3}, {%4,%5,%6,%7}, {%8,%9}, {%0,%1,%2,%3};"
        : "+f"(d[0]), "+f"(d[1]), "+f"(d[2]), "+f"(d[3])
        : "r"(a[0]), "r"(a[1]), "r"(a[2]), "r"(a[3]), "r"(b[0]), "r"(b[1]));
}

// ---------------------------------------------------------------------------
// SMEM layout (dynamic):
//  a_hi/a_lo: [128 m][68 k]   bank (4g+r): conflict-free fragment reads
//  b_hi/b_lo: [64 k][136 n]   bank (8r+g): conflict-free fragment reads
//                             (was 132 -> (4r+g) 2-way conflict)
// ---------------------------------------------------------------------------
#define A_LD 68
#define B_LD 136
#define SM_AH 0
#define SM_AL (SM_AH + ROWS * A_LD * 4)            // 34816
#define SM_BH (SM_AL + ROWS * A_LD * 4)            // 69632
#define SM_BL (SM_BH + BK * B_LD * 4)              // 104448
#define SMEM_TOTAL (SM_BL + BK * B_LD * 4)         // 139264

// Broadcast staging (reuses GEMM smem): 8 copies of one 4 KB z-row = 32 KB
#define NCOPY 8

// ---------------------------------------------------------------------------
// One split-K GEMM job: g_P[ks][0:128][j0:+128] = A[:, k-slice] @ W[slice, cols]
// CTA id -> (jt = id & 7, ks = id >> 3). 8 warps as 4(M) x 2(N), tile 32x64.
// 3-pass tf32 hi/lo for fp32-grade accuracy.
// ---------------------------------------------------------------------------
__device__ void gemm_job(const float* __restrict__ A,
                         const float* __restrict__ W,
                         int ldw, int woff, char* sm)
{
    float* a_hi = (float*)(sm + SM_AH);
    float* a_lo = (float*)(sm + SM_AL);
    float* b_hi = (float*)(sm + SM_BH);
    float* b_lo = (float*)(sm + SM_BL);

    const int tid  = threadIdx.x;
    const int wid  = tid >> 5;
    const int lane = tid & 31;
    const int j0   = (blockIdx.x & (NTILE - 1)) * BN;
    const int ks0  = blockIdx.x >> 3;
    const int k0   = ks0 * BK;

    // --- Stage A tile [128 m][64 k] as tf32 hi/lo ---
    {
        const int row = tid >> 1;
        const int kb  = (tid & 1) * 32;
        const float* ap = A + (size_t)row * DMODEL + k0 + kb;
        float* dh = a_hi + row * A_LD + kb;
        float* dl = a_lo + row * A_LD + kb;
#pragma unroll
        for (int c = 0; c < 8; c++) {
            float4 f = *(const float4*)(ap + c * 4);
            uint32_t h[4], l[4];
            cvt_hilo(f.x, h[0], l[0]);
            cvt_hilo(f.y, h[1], l[1]);
            cvt_hilo(f.z, h[2], l[2]);
            cvt_hilo(f.w, h[3], l[3]);
            *(uint4*)(dh + c * 4) = make_uint4(h[0], h[1], h[2], h[3]);
            *(uint4*)(dl + c * 4) = make_uint4(l[0], l[1], l[2], l[3]);
        }
    }

    // --- Stage W tile [64 k][128 n] as tf32 hi/lo (coalesced) ---
    {
        const int kl = tid >> 5;
        const int n  = (tid & 31) * 4;
#pragma unroll
        for (int it = 0; it < 8; it++) {
            const int k = it * 8 + kl;
            float4 f = *(const float4*)(W + (size_t)(k0 + k) * ldw + woff + j0 + n);
            uint32_t h[4], l[4];
            cvt_hilo(f.x, h[0], l[0]);
            cvt_hilo(f.y, h[1], l[1]);
            cvt_hilo(f.z, h[2], l[2]);
            cvt_hilo(f.w, h[3], l[3]);
            *(uint4*)(b_hi + k * B_LD + n) = make_uint4(h[0], h[1], h[2], h[3]);
            *(uint4*)(b_lo + k * B_LD + n) = make_uint4(l[0], l[1], l[2], l[3]);
        }
    }
    __syncthreads();

    const int m0 = (wid >> 1) * 32;
    const int n0 = (wid & 1) * 64;
    const int g  = lane >> 2;
    const int r  = lane & 3;

    float acc[2][8][4];
#pragma unroll
    for (int mt = 0; mt < 2; mt++)
#pragma unroll
        for (int nt = 0; nt < 8; nt++)
#pragma unroll
            for (int i = 0; i < 4; i++) acc[mt][nt][i] = 0.0f;

    const uint32_t* ah_s = (const uint32_t*)a_hi;
    const uint32_t* al_s = (const uint32_t*)a_lo;
    const uint32_t* bh_s = (const uint32_t*)b_hi;
    const uint32_t* bl_s = (const uint32_t*)b_lo;

#pragma unroll
    for (int ks = 0; ks < 8; ks++) {
        const int kk = ks * 8 + r;
        uint32_t ah[2][4], al[2][4];
#pragma unroll
        for (int mt = 0; mt < 2; mt++) {
            const int mrow = m0 + mt * 16 + g;
            ah[mt][0] = ah_s[mrow * A_LD + kk];
            ah[mt][1] = ah_s[(mrow + 8) * A_LD + kk];
            ah[mt][2] = ah_s[mrow * A_LD + kk + 4];
            ah[mt][3] = ah_s[(mrow + 8) * A_LD + kk + 4];
            al[mt][0] = al_s[mrow * A_LD + kk];
            al[mt][1] = al_s[(mrow + 8) * A_LD + kk];
            al[mt][2] = al_s[mrow * A_LD + kk + 4];
            al[mt][3] = al_s[(mrow + 8) * A_LD + kk + 4];
        }
#pragma unroll
        for (int nt = 0; nt < 8; nt++) {
            const int ncol = n0 + nt * 8 + g;
            uint32_t bh[2], bl[2];
            bh[0] = bh_s[(ks * 8 + r) * B_LD + ncol];
            bh[1] = bh_s[(ks * 8 + r + 4) * B_LD + ncol];
            bl[0] = bl_s[(ks * 8 + r) * B_LD + ncol];
            bl[1] = bl_s[(ks * 8 + r + 4) * B_LD + ncol];
#pragma unroll
            for (int mt = 0; mt < 2; mt++) {
                mma_tf32(acc[mt][nt], ah[mt], bh);   // hi*hi
                mma_tf32(acc[mt][nt], ah[mt], bl);   // hi*lo
                mma_tf32(acc[mt][nt], al[mt], bh);   // lo*hi
            }
        }
    }

    float* pbase = g_P + (size_t)ks0 * (ROWS * DMODEL) + j0;
#pragma unroll
    for (int mt = 0; mt < 2; mt++) {
        const int mrow = m0 + mt * 16 + g;
#pragma unroll
        for (int nt = 0; nt < 8; nt++) {
            const int ncol = n0 + nt * 8 + 2 * r;
            *(float2*)(pbase + (size_t)mrow * DMODEL + ncol) =
                make_float2(acc[mt][nt][0], acc[mt][nt][1]);
            *(float2*)(pbase + (size_t)(mrow + 8) * DMODEL + ncol) =
                make_float2(acc[mt][nt][2], acc[mt][nt][3]);
        }
    }
    __syncthreads();   // smem reuse safety before next phase
}

// Reduce 16 partials + bias -> dst. 32768 float4 over 32768 threads (MLP 16).
__device__ void reduce_job(const float* __restrict__ bias, int boff, float* dst)
{
    const int idx = blockIdx.x * 256 + threadIdx.x;      // 0..32767 float4
    const int col = (idx & (DMODEL / 4 - 1)) * 4;

    const float* bp = bias + boff + col;
    float4 s = make_float4(__ldg(bp), __ldg(bp + 1), __ldg(bp + 2), __ldg(bp + 3));

    const float4* pp = (const float4*)g_P + idx;
#pragma unroll
    for (int p = 0; p < KSPLIT; p++) {
        const float4 v = pp[(size_t)p * (ROWS * DMODEL / 4)];
        s.x += v.x; s.y += v.y; s.z += v.z; s.w += v.w;
    }
    ((float4*)dst)[idx] = s;
}

// ---------------------------------------------------------------------------
// Persistent fused kernel: gemm1 | reduce+bkv | gemm2 | reduce+bo | broadcast
// 128 CTAs, 139 KB smem -> 1 CTA/SM, whole grid wave-1 resident on 148 SMs.
// ---------------------------------------------------------------------------
__global__ __launch_bounds__(256, 1)
void fused_all(const float* __restrict__ context,
               const float* __restrict__ Wkv,
               const float* __restrict__ bkv,
               const float* __restrict__ Wo,
               const float* __restrict__ bo,
               float* __restrict__ out)
{
    extern __shared__ char sm[];

    // Phase A: v-partials = context @ Wkv[:, 1024:2048]
    gemm_job(context, Wkv, 2 * DMODEL, DMODEL, sm);
    grid_barrier(0);

    // Phase B: g_V = sum(partials) + bkv[1024:]
    reduce_job(bkv, DMODEL, g_V);
    grid_barrier(1);

    // Phase C: z-partials = g_V @ Wo
    gemm_job(g_V, Wo, DMODEL, 0, sm);
    grid_barrier(2);

    // Phase D: g_Z = sum(partials) + bo
    reduce_job(bo, 0, g_Z);
    grid_barrier(3);

    // Phase E: broadcast via TMA bulk stores. Stage NCOPY copies of this
    // CTA's z-row in smem, then stream 32 x (NCOPY*4KB) async bulk copies.
    // Replaces 2048 STG.128/CTA (outstanding-store-depth-bound) with deeply
    // pipelined cp.async.bulk traffic.
    {
        const int gg = blockIdx.x;              // 0..127
        const int t  = threadIdx.x;             // float4 column
        float4* zbuf = (float4*)sm;             // 32 KB staging, reuses GEMM smem

        const float4 zv = __ldg((const float4*)g_Z + (size_t)gg * (DMODEL / 4) + t);
#pragma unroll
        for (int c = 0; c < NCOPY; c++)
            zbuf[c * (DMODEL / 4) + t] = zv;
        __syncthreads();
        asm volatile("fence.proxy.async.shared::cta;" ::: "memory");

        if (t == 0) {
            const uint32_t saddr = smem_u32(zbuf);
            float* gbase = out + (size_t)gg * TPF * DMODEL;
            const uint32_t chunk = NCOPY * DMODEL * 4;   // 32 KB
#pragma unroll 4
            for (int i = 0; i < TPF / NCOPY; i++) {      // 32 chunks
                asm volatile(
                    "cp.async.bulk.global.shared::cta.bulk_group [%0], [%1], %2;"
                    :: "l"(gbase + (size_t)i * NCOPY * DMODEL), "r"(saddr), "r"(chunk)
                    : "memory");
            }
            asm volatile("cp.async.bulk.commit_group;" ::: "memory");
            asm volatile("cp.async.bulk.wait_group 0;" ::: "memory");
        }
        // issuing thread has drained all bulk stores; other threads may exit
    }
}

// ---------------------------------------------------------------------------
// Inputs (metadata order): 0:x 1:context 2:Wq 3:bq 4:Wkv 5:bkv 6:Wo 7:bo
// x, Wq, bq are DEAD in the reference (q is never used).
// ---------------------------------------------------------------------------
extern "C" void kernel_launch(void* const* d_in, const int* in_sizes, int n_in,
                              void* d_out, int out_size)
{
    (void)in_sizes; (void)n_in; (void)out_size;

    const float* context = (const float*)d_in[1];
    const float* Wkv     = (const float*)d_in[4];
    const float* bkv     = (const float*)d_in[5];
    const float* Wo      = (const float*)d_in[6];
    const float* bo      = (const float*)d_in[7];
    float* out           = (float*)d_out;

    static bool attr_set = false;
    if (!attr_set) {
        cudaFuncSetAttribute(fused_all, cudaFuncAttributeMaxDynamicSharedMemorySize, SMEM_TOTAL);
        attr_set = true;
    }

    fused_all<<<GRID, 256, SMEM_TOTAL>>>(context, Wkv, bkv, Wo, bo, out);
}

// round 14
// speedup vs baseline: 1.0481x; 1.0481x over previous
#include <cuda_runtime.h>
#include <cstdint>

// Problem constants (fixed by setup_inputs: B=2, Lq=16384, D=1024, M=64, H=16)
#define DMODEL 1024
#define ROWS   128            // B*M flattened rows
#define TPF    256            // Lq / M  (tokens per frame)

#define KSPLIT 16             // split-K factor
#define BK     64             // K per GEMM job
#define BN     128            // cols per GEMM job
#define NTILE  (DMODEL / BN)  // 8 column tiles
#define GRID   128            // persistent CTAs (= NTILE * KSPLIT)
#define NTHR   512            // threads per CTA (16 warps, 4/SMSP)

// Scratch (static __device__ arrays — no runtime allocation)
__device__ float g_P[KSPLIT * ROWS * DMODEL];  // split-K partials (8 MB)
__device__ float g_V[ROWS * DMODEL];           // v = context @ Wkv_v + bkv_v
__device__ float g_Z[ROWS * DMODEL];           // z = v @ Wo + bo

// Grid-barrier state. MONOTONIC across launches — never reset (reset scheme
// deadlocked: a CTA still polling in the spin loop could observe the zeroed
// counter). Each launch's cohort releases at the next multiple of GRID.
__device__ unsigned g_bar[8];

__device__ __forceinline__ void grid_barrier(int ph) {
    __syncthreads();
    if (threadIdx.x == 0) {
        __threadfence();                                   // release prior writes
        const unsigned my = atomicAdd(&g_bar[ph], 1u) + 1u;
        const unsigned target = ((my + GRID - 1u) / GRID) * GRID;
        while (*(volatile unsigned*)&g_bar[ph] < target) { __nanosleep(32); }
        __threadfence();                                   // acquire others' writes
    }
    __syncthreads();
}

// ---------------------------------------------------------------------------
// tf32 helpers (mma.sync — baseline PTX, works at compute_100)
// ---------------------------------------------------------------------------
__device__ __forceinline__ uint32_t f2tf32(float f) {
    uint32_t r;
    asm("cvt.rna.tf32.f32 %0, %1;" : "=r"(r) : "f"(f));
    return r;
}
__device__ __forceinline__ void cvt_hilo(float f, uint32_t& hi, uint32_t& lo) {
    hi = f2tf32(f);
    lo = f2tf32(f - __uint_as_float(hi));
}
__device__ __forceinline__ void mma_tf32(float* d, const uint32_t* a, const uint32_t* b) {
    asm volatile(
        "mma.sync.aligned.m16n8k8.row.col.f32.tf32.tf32.f32 "
        "{%0,%1,%2,%3}, {%4,%5,%6,%7}, {%8,%9}, {%0,%1,%2,%3};"
        : "+f"(d[0]), "+f"(d[1]), "+f"(d[2]), "+f"(d[3])
        : "r"(a[0]), "r"(a[1]), "r"(a[2]), "r"(a[3]), "r"(b[0]), "r"(b[1]));
}

// ---------------------------------------------------------------------------
// SMEM layout (dynamic):
//  a_hi/a_lo: [128 m][68 k]   bank (4g+r): conflict-free fragment reads
//  b_hi/b_lo: [64 k][136 n]   bank (8r+8nt+g): conflict-free fragment reads
// ---------------------------------------------------------------------------
#define A_LD 68
#define B_LD 136
#define SM_AH 0
#define SM_AL (SM_AH + ROWS * A_LD * 4)            // 34816
#define SM_BH (SM_AL + ROWS * A_LD * 4)            // 69632
#define SM_BL (SM_BH + BK * B_LD * 4)              // 104448
#define SMEM_TOTAL (SM_BL + BK * B_LD * 4)         // 139264

// ---------------------------------------------------------------------------
// One split-K GEMM job: g_P[ks][0:128][j0:+128] = A[:, k-slice] @ W[slice, cols]
// CTA id -> (jt = id & 7, ks = id >> 3). 16 warps as 4(M) x 4(N), tile 32x32.
// 3-pass tf32 hi/lo for fp32-grade accuracy.
// ---------------------------------------------------------------------------
__device__ void gemm_job(const float* __restrict__ A,
                         const float* __restrict__ W,
                         int ldw, int woff, char* sm)
{
    float* a_hi = (float*)(sm + SM_AH);
    float* a_lo = (float*)(sm + SM_AL);
    float* b_hi = (float*)(sm + SM_BH);
    float* b_lo = (float*)(sm + SM_BL);

    const int tid  = threadIdx.x;
    const int wid  = tid >> 5;
    const int lane = tid & 31;
    const int j0   = (blockIdx.x & (NTILE - 1)) * BN;
    const int ks0  = blockIdx.x >> 3;
    const int k0   = ks0 * BK;

    // --- Stage A tile [128 m][64 k] as tf32 hi/lo (512 thr: 16 floats each) ---
    {
        const int row = tid >> 2;
        const int kb  = (tid & 3) * 16;
        const float* ap = A + (size_t)row * DMODEL + k0 + kb;
        float* dh = a_hi + row * A_LD + kb;
        float* dl = a_lo + row * A_LD + kb;
#pragma unroll
        for (int c = 0; c < 4; c++) {
            float4 f = *(const float4*)(ap + c * 4);
            uint32_t h[4], l[4];
            cvt_hilo(f.x, h[0], l[0]);
            cvt_hilo(f.y, h[1], l[1]);
            cvt_hilo(f.z, h[2], l[2]);
            cvt_hilo(f.w, h[3], l[3]);
            *(uint4*)(dh + c * 4) = make_uint4(h[0], h[1], h[2], h[3]);
            *(uint4*)(dl + c * 4) = make_uint4(l[0], l[1], l[2], l[3]);
        }
    }

    // --- Stage W tile [64 k][128 n] as tf32 hi/lo (coalesced, 16 k-rows/pass) ---
    {
        const int kl = tid >> 5;          // 0..15
        const int n  = (tid & 31) * 4;
#pragma unroll
        for (int it = 0; it < 4; it++) {
            const int k = it * 16 + kl;
            float4 f = *(const float4*)(W + (size_t)(k0 + k) * ldw + woff + j0 + n);
            uint32_t h[4], l[4];
            cvt_hilo(f.x, h[0], l[0]);
            cvt_hilo(f.y, h[1], l[1]);
            cvt_hilo(f.z, h[2], l[2]);
            cvt_hilo(f.w, h[3], l[3]);
            *(uint4*)(b_hi + k * B_LD + n) = make_uint4(h[0], h[1], h[2], h[3]);
            *(uint4*)(b_lo + k * B_LD + n) = make_uint4(l[0], l[1], l[2], l[3]);
        }
    }
    __syncthreads();

    const int m0 = (wid >> 2) * 32;      // 4 M-groups
    const int n0 = (wid & 3) * 32;       // 4 N-groups
    const int g  = lane >> 2;
    const int r  = lane & 3;

    float acc[2][4][4];
#pragma unroll
    for (int mt = 0; mt < 2; mt++)
#pragma unroll
        for (int nt = 0; nt < 4; nt++)
#pragma unroll
            for (int i = 0; i < 4; i++) acc[mt][nt][i] = 0.0f;

    const uint32_t* ah_s = (const uint32_t*)a_hi;
    const uint32_t* al_s = (const uint32_t*)a_lo;
    const uint32_t* bh_s = (const uint32_t*)b_hi;
    const uint32_t* bl_s = (const uint32_t*)b_lo;

#pragma unroll
    for (int ks = 0; ks < 8; ks++) {
        const int kk = ks * 8 + r;
        uint32_t ah[2][4], al[2][4];
#pragma unroll
        for (int mt = 0; mt < 2; mt++) {
            const int mrow = m0 + mt * 16 + g;
            ah[mt][0] = ah_s[mrow * A_LD + kk];
            ah[mt][1] = ah_s[(mrow + 8) * A_LD + kk];
            ah[mt][2] = ah_s[mrow * A_LD + kk + 4];
            ah[mt][3] = ah_s[(mrow + 8) * A_LD + kk + 4];
            al[mt][0] = al_s[mrow * A_LD + kk];
            al[mt][1] = al_s[(mrow + 8) * A_LD + kk];
            al[mt][2] = al_s[mrow * A_LD + kk + 4];
            al[mt][3] = al_s[(mrow + 8) * A_LD + kk + 4];
        }
#pragma unroll
        for (int nt = 0; nt < 4; nt++) {
            const int ncol = n0 + nt * 8 + g;
            uint32_t bh[2], bl[2];
            bh[0] = bh_s[(ks * 8 + r) * B_LD + ncol];
            bh[1] = bh_s[(ks * 8 + r + 4) * B_LD + ncol];
            bl[0] = bl_s[(ks * 8 + r) * B_LD + ncol];
            bl[1] = bl_s[(ks * 8 + r + 4) * B_LD + ncol];
#pragma unroll
            for (int mt = 0; mt < 2; mt++) {
                mma_tf32(acc[mt][nt], ah[mt], bh);   // hi*hi
                mma_tf32(acc[mt][nt], ah[mt], bl);   // hi*lo
                mma_tf32(acc[mt][nt], al[mt], bh);   // lo*hi
            }
        }
    }

    float* pbase = g_P + (size_t)ks0 * (ROWS * DMODEL) + j0;
#pragma unroll
    for (int mt = 0; mt < 2; mt++) {
        const int mrow = m0 + mt * 16 + g;
#pragma unroll
        for (int nt = 0; nt < 4; nt++) {
            const int ncol = n0 + nt * 8 + 2 * r;
            *(float2*)(pbase + (size_t)mrow * DMODEL + ncol) =
                make_float2(acc[mt][nt][0], acc[mt][nt][1]);
            *(float2*)(pbase + (size_t)(mrow + 8) * DMODEL + ncol) =
                make_float2(acc[mt][nt][2], acc[mt][nt][3]);
        }
    }
    __syncthreads();   // smem reuse safety before next phase
}

// ---------------------------------------------------------------------------
// Reduce 16 partials + bias -> dst. 256 float4 per CTA over 512 threads:
// halves each sum 8 slices, deterministic smem combine (bias + lo8 + hi8).
// ---------------------------------------------------------------------------
__device__ void reduce_job(const float* __restrict__ bias, int boff, float* dst, char* sm)
{
    float4* red = (float4*)sm;                            // 256 * 16 B = 4 KB

    const int tid  = threadIdx.x;
    const int el   = tid & 255;
    const int half = tid >> 8;                            // 0 or 1
    const int idx  = blockIdx.x * 256 + el;               // float4 index

    const float4* pp = (const float4*)g_P + (size_t)half * 8 * (ROWS * DMODEL / 4) + idx;
    float4 s = make_float4(0.f, 0.f, 0.f, 0.f);
#pragma unroll
    for (int p = 0; p < 8; p++) {
        const float4 v = pp[(size_t)p * (ROWS * DMODEL / 4)];
        s.x += v.x; s.y += v.y; s.z += v.z; s.w += v.w;
    }

    if (half == 1) red[el] = s;
    __syncthreads();
    if (half == 0) {
        const int col = (idx & (DMODEL / 4 - 1)) * 4;
        const float* bp = bias + boff + col;
        const float4 hi = red[el];
        float4 acc = make_float4(__ldg(bp)     + s.x + hi.x,
                                 __ldg(bp + 1) + s.y + hi.y,
                                 __ldg(bp + 2) + s.z + hi.z,
                                 __ldg(bp + 3) + s.w + hi.w);
        ((float4*)dst)[idx] = acc;
    }
    __syncthreads();   // smem reuse safety
}

// ---------------------------------------------------------------------------
// Persistent fused kernel: gemm1 | reduce+bkv | gemm2 | reduce+bo | broadcast
// 128 CTAs x 512 thr, 139 KB smem -> 1 CTA/SM, whole grid wave-1 resident.
// ---------------------------------------------------------------------------
__global__ __launch_bounds__(NTHR, 1)
void fused_all(const float* __restrict__ context,
               const float* __restrict__ Wkv,
               const float* __restrict__ bkv,
               const float* __restrict__ Wo,
               const float* __restrict__ bo,
               float* __restrict__ out)
{
    extern __shared__ char sm[];

    // Phase A: v-partials = context @ Wkv[:, 1024:2048]
    gemm_job(context, Wkv, 2 * DMODEL, DMODEL, sm);
    grid_barrier(0);

    // Phase B: g_V = sum(partials) + bkv[1024:]
    reduce_job(bkv, DMODEL, g_V, sm);
    grid_barrier(1);

    // Phase C: z-partials = g_V @ Wo
    gemm_job(g_V, Wo, DMODEL, 0, sm);
    grid_barrier(2);

    // Phase D: g_Z = sum(partials) + bo
    reduce_job(bo, 0, g_Z, sm);
    grid_barrier(3);

    // Phase E: broadcast — 512 threads: thread (col, half) streams 128 rows
    {
        const int gg   = blockIdx.x;            // 0..127
        const int col  = threadIdx.x & 255;     // float4 column
        const int half = threadIdx.x >> 8;      // 0 or 1 (row half)

        const float4 s = __ldg((const float4*)g_Z + (size_t)gg * (DMODEL / 4) + col);
        float4* op = (float4*)out +
                     ((size_t)gg * TPF + (size_t)half * (TPF / 2)) * (DMODEL / 4) + col;
#pragma unroll 8
        for (int r = 0; r < TPF / 2; r++)
            op[(size_t)r * (DMODEL / 4)] = s;
    }
}

// ---------------------------------------------------------------------------
// Inputs (metadata order): 0:x 1:context 2:Wq 3:bq 4:Wkv 5:bkv 6:Wo 7:bo
// x, Wq, bq are DEAD in the reference (q is never used).
// ---------------------------------------------------------------------------
extern "C" void kernel_launch(void* const* d_in, const int* in_sizes, int n_in,
                              void* d_out, int out_size)
{
    (void)in_sizes; (void)n_in; (void)out_size;

    const float* context = (const float*)d_in[1];
    const float* Wkv     = (const float*)d_in[4];
    const float* bkv     = (const float*)d_in[5];
    const float* Wo      = (const float*)d_in[6];
    const float* bo      = (const float*)d_in[7];
    float* out           = (float*)d_out;

    static bool attr_set = false;
    if (!attr_set) {
        cudaFuncSetAttribute(fused_all, cudaFuncAttributeMaxDynamicSharedMemorySize, SMEM_TOTAL);
        attr_set = true;
    }

    fused_all<<<GRID, NTHR, SMEM_TOTAL>>>(context, Wkv, bkv, Wo, bo, out);
}